// round 16
// baseline (speedup 1.0000x reference)
#include <cuda_runtime.h>
#include <cuda_bf16.h>
#include <cstdint>

// Problem constants (fixed by setup_inputs)
#define NN 200000      // nodes
#define NE 800000      // edges
#define HH 128         // hidden
#define NG 8000        // graphs
#define AF 39          // atom feature dim
#define BF 11          // bond feature dim
#define KI 50          // AF+BF
#define KO 167         // AF+HH
#define DEPTH 6
#define TE2 64         // edges per tensor tile
#define NTT (NE / TE2) // 12500
#define GRID_TC 296

#define SPAD 136       // bf16 tile row stride (elements); 272B rows
#define FPAD 132       // f32 staging row stride (elements)

// fused-step smem: [Wh_hi 34816][Wh_lo 34816][msg_hi 17408][msg_lo 17408]
#define OFF_WHL 34816
#define OFF_MH  69632
#define OFF_ML  87040
#define OFF_STG 69632
#define TC_SMEM 104448

// merged mk+step0 smem: Wi hi/lo + Wh hi/lo + msg hi/lo (stg overlays msg)
#define MS_WIL 34816
#define MS_WHH 69632
#define MS_WHL 104448
#define MS_MH  139264
#define MS_ML  156672
#define MS_STG 139264
#define MS_SMEM 174080

// node_out MMA tile geometry: K padded 167 -> 176, stride 184 elems (368 B)
#define SP2 184
#define N_OFF_WHL 47104
#define N_OFF_MH  94208
#define N_OFF_ML  117760
#define N_OFF_STG 94208
#define N_SMEM    141312

// ---------------- scratch (device globals; no allocations allowed) ----------
__device__ float g_msg_input[(size_t)NE * HH];
__device__ float g_Z0[(size_t)NE * HH];
__device__ float g_Z1[(size_t)NE * HH];
__device__ float g_nZ0[(size_t)NN * HH];
__device__ float g_nZ1[(size_t)NN * HH];
__device__ float g_nZ2[(size_t)NN * HH];
__device__ float g_m[(size_t)NN * HH];
__device__ float g_inv[NG];
__device__ int   g_cnt[NG];

// ---------------- mma.sync / ldmatrix helpers (arch-agnostic PTX) ------------
__device__ __forceinline__ uint32_t smem_u32(const void* p) {
    uint32_t a;
    asm("{ .reg .u64 t; cvta.to.shared.u64 t, %1; cvt.u32.u64 %0, t; }"
        : "=r"(a) : "l"(p));
    return a;
}
#define LDSM_X4(r0, r1, r2, r3, addr) \
    asm volatile("ldmatrix.sync.aligned.m8n8.x4.shared.b16 {%0,%1,%2,%3}, [%4];" \
        : "=r"(r0), "=r"(r1), "=r"(r2), "=r"(r3) : "r"(addr))
#define LDSM_X2(r0, r1, addr) \
    asm volatile("ldmatrix.sync.aligned.m8n8.x2.shared.b16 {%0,%1}, [%2];" \
        : "=r"(r0), "=r"(r1) : "r"(addr))

__device__ __forceinline__ void mma_bf16(float* d, const uint32_t* a,
                                         const uint32_t* b) {
    asm volatile(
        "mma.sync.aligned.m16n8k16.row.col.f32.bf16.bf16.f32 "
        "{%0,%1,%2,%3}, {%4,%5,%6,%7}, {%8,%9}, {%0,%1,%2,%3};"
        : "+f"(d[0]), "+f"(d[1]), "+f"(d[2]), "+f"(d[3])
        : "r"(a[0]), "r"(a[1]), "r"(a[2]), "r"(a[3]), "r"(b[0]), "r"(b[1]));
}

__device__ __forceinline__ unsigned bfpair(float lo, float hi) {
    unsigned r;
    asm("cvt.rn.bf16x2.f32 %0, %1, %2;" : "=r"(r) : "f"(hi), "f"(lo));
    return r;
}
__device__ __forceinline__ unsigned long long pku(unsigned a, unsigned b) {
    unsigned long long r;
    asm("mov.b64 %0, {%1, %2};" : "=l"(r) : "r"(a), "r"(b));
    return r;
}
// split float4 into hi/lo bf16 quads, store row-major stride SPAD at (row, col4)
__device__ __forceinline__ void split_store(char* mh, char* ml, int row, int col4,
                                            float4 v) {
    __nv_bfloat16 b0 = __float2bfloat16_rn(v.x), b1 = __float2bfloat16_rn(v.y);
    __nv_bfloat16 b2 = __float2bfloat16_rn(v.z), b3 = __float2bfloat16_rn(v.w);
    unsigned hp01 = (unsigned)__bfloat16_as_ushort(b0)
                  | ((unsigned)__bfloat16_as_ushort(b1) << 16);
    unsigned hp23 = (unsigned)__bfloat16_as_ushort(b2)
                  | ((unsigned)__bfloat16_as_ushort(b3) << 16);
    float l0 = v.x - __bfloat162float(b0), l1 = v.y - __bfloat162float(b1);
    float l2 = v.z - __bfloat162float(b2), l3 = v.w - __bfloat162float(b3);
    uint32_t off = (uint32_t)row * (SPAD * 2) + (uint32_t)col4 * 2;
    *(unsigned long long*)(mh + off) = pku(hp01, hp23);
    *(unsigned long long*)(ml + off) = pku(bfpair(l0, l1), bfpair(l2, l3));
}
// same but parameterized stride (elements)
__device__ __forceinline__ void split_store_s(char* mh, char* ml, int row, int col4,
                                              float4 v, int spad) {
    __nv_bfloat16 b0 = __float2bfloat16_rn(v.x), b1 = __float2bfloat16_rn(v.y);
    __nv_bfloat16 b2 = __float2bfloat16_rn(v.z), b3 = __float2bfloat16_rn(v.w);
    unsigned hp01 = (unsigned)__bfloat16_as_ushort(b0)
                  | ((unsigned)__bfloat16_as_ushort(b1) << 16);
    unsigned hp23 = (unsigned)__bfloat16_as_ushort(b2)
                  | ((unsigned)__bfloat16_as_ushort(b3) << 16);
    float l0 = v.x - __bfloat162float(b0), l1 = v.y - __bfloat162float(b1);
    float l2 = v.z - __bfloat162float(b2), l3 = v.w - __bfloat162float(b3);
    uint32_t off = (uint32_t)row * (spad * 2) + (uint32_t)col4 * 2;
    *(unsigned long long*)(mh + off) = pku(hp01, hp23);
    *(unsigned long long*)(ml + off) = pku(bfpair(l0, l1), bfpair(l2, l3));
}

// ---------------- small kernels ---------------------------------------------
// prep: per-graph node count + zero nZ0 (grid-stride both)
__global__ void prep_k(const int* __restrict__ gid, int* __restrict__ cnt,
                       float* __restrict__ nZzero) {
    int i0 = blockIdx.x * 256 + threadIdx.x;
    for (int v = i0; v < NN; v += gridDim.x * 256)
        atomicAdd(&cnt[gid[v]], 1);
    float4* zz = reinterpret_cast<float4*>(nZzero);
    float4 z4 = make_float4(0.f, 0.f, 0.f, 0.f);
    for (int i = i0; i < NN * 32; i += gridDim.x * 256)
        __stcs(zz + i, z4);
}
__global__ void inv_k(const int* __restrict__ cnt, float* __restrict__ inv) {
    int g = blockIdx.x * 256 + threadIdx.x;
    if (g < NG) inv[g] = 1.0f / fmaxf((float)cnt[g], 1.0f);
}

// ============ shared MMA core: 64 rows x 128 cols, 2Mx4N warp split =========
#define MMA_CORE(NKK, spadv, whib, whilb, mhb, mlb)                            \
    float acc[2][4][4];                                                        \
    _Pragma("unroll")                                                          \
    for (int rt = 0; rt < 2; rt++)                                             \
        _Pragma("unroll")                                                      \
        for (int jj = 0; jj < 4; jj++) {                                       \
            acc[rt][jj][0] = 0.f; acc[rt][jj][1] = 0.f;                        \
            acc[rt][jj][2] = 0.f; acc[rt][jj][3] = 0.f;                        \
        }                                                                      \
    _Pragma("unroll 1")                                                        \
    for (int kk = 0; kk < NKK; kk++) {                                         \
        uint32_t koff = (uint32_t)kk * 32;                                     \
        uint32_t bh[4][2], bl[4][2];                                           \
        _Pragma("unroll")                                                      \
        for (int jj = 0; jj < 4; jj++) {                                       \
            uint32_t boff = b_off + (uint32_t)(8 * jj) * (spadv * 2) + koff;   \
            LDSM_X2(bh[jj][0], bh[jj][1], whib + boff);                        \
            LDSM_X2(bl[jj][0], bl[jj][1], whilb + boff);                       \
        }                                                                      \
        _Pragma("unroll")                                                      \
        for (int rt = 0; rt < 2; rt++) {                                       \
            uint32_t aaddr = a_off + (uint32_t)(16 * rt) * (spadv * 2) + koff; \
            uint32_t ah[4], al[4];                                             \
            LDSM_X4(ah[0], ah[1], ah[2], ah[3], mhb + aaddr);                  \
            LDSM_X4(al[0], al[1], al[2], al[3], mlb + aaddr);                  \
            _Pragma("unroll")                                                  \
            for (int jj = 0; jj < 4; jj++) {                                   \
                mma_bf16(acc[rt][jj], ah, bh[jj]);                             \
                mma_bf16(acc[rt][jj], ah, bl[jj]);                             \
                mma_bf16(acc[rt][jj], al, bh[jj]);                             \
            }                                                                  \
        }                                                                      \
    }

#define STAGE_ACC()                                                            \
    _Pragma("unroll")                                                          \
    for (int rt = 0; rt < 2; rt++)                                             \
        _Pragma("unroll")                                                      \
        for (int jj = 0; jj < 4; jj++) {                                       \
            int col = 32 * wn + 8 * jj + t2;                                   \
            int r0 = 32 * wm + 16 * rt + g;                                    \
            *reinterpret_cast<float2*>(stg + r0 * FPAD + col)                  \
                = make_float2(acc[rt][jj][0], acc[rt][jj][1]);                 \
            *reinterpret_cast<float2*>(stg + (r0 + 8) * FPAD + col)           \
                = make_float2(acc[rt][jj][2], acc[rt][jj][3]);                 \
        }

// ---------------- merged: msg_input build + fused step 0 ---------------------
// Per tile: features -> Wi-MMA -> mi (store fp32, keep in regs) ->
// relu -> msg0 tile -> Wh-MMA -> Z0 store + RED nodeZ0.
// Also zeroes nZ1 (step 1's RED target) at entry. 1 block/SM (170 KB smem).
__global__ __launch_bounds__(256, 1) void mk_step0_mma(
    const float* __restrict__ atom_x, const float* __restrict__ bond_x,
    const int* __restrict__ srcp, const int* __restrict__ dstp,
    const float* __restrict__ Wi, const float* __restrict__ Wh,
    float* __restrict__ mi, float* __restrict__ Zo, float* __restrict__ nZo,
    float* __restrict__ nZzero)
{
    extern __shared__ char smc[];
    char* wih = smc;
    char* wil = smc + MS_WIL;
    char* whh = smc + MS_WHH;
    char* whl = smc + MS_WHL;
    char* mh  = smc + MS_MH;
    char* ml  = smc + MS_ML;
    float* stg = (float*)(smc + MS_STG);

    int tid = threadIdx.x, lane = tid & 31, wid = tid >> 5;
    int wm = wid >> 2, wn = wid & 3;

    // zero step 1's nodeZ RED target
    {
        float4* zz = reinterpret_cast<float4*>(nZzero);
        float4 z4 = make_float4(0.f, 0.f, 0.f, 0.f);
        for (int i = blockIdx.x * 256 + tid; i < NN * 32; i += gridDim.x * 256)
            __stcs(zz + i, z4);
    }

    // Wi (fp32 [128][50]) -> bf16 hi/lo tiles, cols padded to 64
    for (int idx = tid; idx < 128 * 16; idx += 256) {
        int n = idx >> 4, c4 = (idx & 15) * 4;
        float4 v;
        v.x = (c4 + 0 < KI) ? Wi[(size_t)n * KI + c4 + 0] : 0.f;
        v.y = (c4 + 1 < KI) ? Wi[(size_t)n * KI + c4 + 1] : 0.f;
        v.z = (c4 + 2 < KI) ? Wi[(size_t)n * KI + c4 + 2] : 0.f;
        v.w = (c4 + 3 < KI) ? Wi[(size_t)n * KI + c4 + 3] : 0.f;
        split_store(wih, wil, n, c4, v);
    }
    // Wh (fp32 [128][128]) -> bf16 hi/lo tiles
    for (int n0 = wid * 16; n0 < wid * 16 + 16; n0++) {
        float4 w = *reinterpret_cast<const float4*>(Wh + (size_t)n0 * HH + lane * 4);
        split_store(whh, whl, n0, lane * 4, w);
    }
    __syncthreads();

    int g = lane >> 2, t2 = (lane & 3) * 2;
    int wrow = wid * 8;

    uint32_t mh_b = smem_u32(mh), ml_b = smem_u32(ml);
    uint32_t wih_b = smem_u32(wih), wil_b = smem_u32(wil);
    uint32_t whh_b = smem_u32(whh), whl_b = smem_u32(whl);
    uint32_t a_off = (uint32_t)(32 * wm + (lane & 15)) * (SPAD * 2)
                   + ((lane >> 4) << 4);
    uint32_t b_off = (uint32_t)(32 * wn + (lane & 7)) * (SPAD * 2)
                   + (((lane >> 3) & 1) << 4);

    for (int t = blockIdx.x; t < NTT; t += gridDim.x) {
        // ---- build feature tile (64 rows x 64 padded cols) ----
#pragma unroll
        for (int i = 0; i < 4; i++) {
            int row = wrow + i * 2 + (lane >> 4);
            int e = t * TE2 + row;
            int s = __ldg(srcp + e);
            int c0 = (lane & 15) * 4;
            float4 v;
#pragma unroll
            for (int c = 0; c < 4; c++) {
                int cc = c0 + c;
                float val = 0.f;
                if (cc < AF)      val = __ldg(atom_x + (size_t)s * AF + cc);
                else if (cc < KI) val = __ldg(bond_x + (size_t)e * BF + (cc - AF));
                (&v.x)[c] = val;
            }
            split_store(mh, ml, row, c0, v);
        }
        __syncthreads();

        // ---- Wi-MMA -> mi ----
        {
            MMA_CORE(4, SPAD, wih_b, wil_b, mh_b, ml_b)
            __syncthreads();
            STAGE_ACC()
        }
        __syncthreads();

        // ---- read staged mi (regs), store fp32 mi ----
        float4 r[8];
#pragma unroll
        for (int i = 0; i < 8; i++) {
            int row = wrow + i;
            int e = t * TE2 + row;
            r[i] = *reinterpret_cast<const float4*>(stg + row * FPAD + lane * 4);
            __stcs(reinterpret_cast<float4*>(mi + (size_t)e * HH + lane * 4), r[i]);
        }
        __syncthreads();   // all stg reads done before msg tile overwrites it

        // ---- relu -> msg0 tile ----
#pragma unroll
        for (int i = 0; i < 8; i++) {
            float4 v = make_float4(fmaxf(r[i].x, 0.f), fmaxf(r[i].y, 0.f),
                                   fmaxf(r[i].z, 0.f), fmaxf(r[i].w, 0.f));
            split_store(mh, ml, wrow + i, lane * 4, v);
        }
        __syncthreads();

        // ---- Wh-MMA -> Z0 ----
        {
            MMA_CORE(8, SPAD, whh_b, whl_b, mh_b, ml_b)
            __syncthreads();
            STAGE_ACC()
        }
        __syncthreads();

        // ---- epilogue: Z0 store + RED nodeZ0 ----
#pragma unroll
        for (int i = 0; i < 8; i++) {
            int row = wrow + i;
            int e = t * TE2 + row;
            int dl = __ldg(dstp + e);
            float4 z = *reinterpret_cast<const float4*>(stg + row * FPAD + lane * 4);
            __stcs(reinterpret_cast<float4*>(Zo + (size_t)e * HH + lane * 4), z);
            atomicAdd(reinterpret_cast<float4*>(nZo + (size_t)dl * HH + lane * 4), z);
        }
        __syncthreads();
    }
}

// ---------------- fused BP step via mma.sync bf16-split (steps 1..4) ---------
__global__ __launch_bounds__(256, 2) void fused_step_mma(
    const float* __restrict__ mi, const float* __restrict__ Zp,
    const float* __restrict__ nZp, float* __restrict__ Zo,
    float* __restrict__ nZo, float* __restrict__ nZzero, int zero_n,
    const float* __restrict__ Wh,
    const int* __restrict__ srcp, const int* __restrict__ dstp, int rev)
{
    extern __shared__ char smc[];
    char* whh = smc;
    char* whl = smc + OFF_WHL;
    char* mh  = smc + OFF_MH;
    char* ml  = smc + OFF_ML;
    float* stg = (float*)(smc + OFF_STG);

    int tid = threadIdx.x, lane = tid & 31, wid = tid >> 5;
    int wm = wid >> 2, wn = wid & 3;

    {
        float4* zz = reinterpret_cast<float4*>(nZzero);
        float4 z4 = make_float4(0.f, 0.f, 0.f, 0.f);
        for (int i = blockIdx.x * 256 + tid; i < zero_n; i += gridDim.x * 256)
            __stcs(zz + i, z4);
    }

    for (int n0 = wid * 16; n0 < wid * 16 + 16; n0++) {
        float4 w = *reinterpret_cast<const float4*>(Wh + (size_t)n0 * HH + lane * 4);
        split_store(whh, whl, n0, lane * 4, w);
    }
    __syncthreads();

    const float4* mi4 = reinterpret_cast<const float4*>(mi);
    const float4* nz4 = reinterpret_cast<const float4*>(nZp);
    const float4* zp4 = reinterpret_cast<const float4*>(Zp);

    int g = lane >> 2, t2 = (lane & 3) * 2;
    int wrow = wid * 8;

    uint32_t mh_b = smem_u32(mh), ml_b = smem_u32(ml);
    uint32_t whh_b = smem_u32(whh), whl_b = smem_u32(whl);
    uint32_t a_off = (uint32_t)(32 * wm + (lane & 15)) * (SPAD * 2)
                   + ((lane >> 4) << 4);
    uint32_t b_off = (uint32_t)(32 * wn + (lane & 7)) * (SPAD * 2)
                   + (((lane >> 3) & 1) << 4);

    for (int it = blockIdx.x; it < NTT; it += gridDim.x) {
        int t = rev ? (NTT - 1 - it) : it;

#pragma unroll
        for (int i = 0; i < 8; i++) {
            int row = wrow + i;
            int e = t * TE2 + row;
            float4 v = __ldcs(mi4 + (size_t)e * 32 + lane);
            int s = __ldg(srcp + e);
            float4 a = __ldg(nz4 + (size_t)s * 32 + lane);
            float4 b = __ldcs(zp4 + (size_t)(e ^ 1) * 32 + lane);
            v.x += a.x - b.x; v.y += a.y - b.y;
            v.z += a.z - b.z; v.w += a.w - b.w;
            v.x = fmaxf(v.x, 0.f); v.y = fmaxf(v.y, 0.f);
            v.z = fmaxf(v.z, 0.f); v.w = fmaxf(v.w, 0.f);
            split_store(mh, ml, row, lane * 4, v);
        }
        __syncthreads();

        MMA_CORE(8, SPAD, whh_b, whl_b, mh_b, ml_b)
        __syncthreads();

        STAGE_ACC()
        __syncthreads();

#pragma unroll
        for (int i = 0; i < 8; i++) {
            int row = wrow + i;
            int e = t * TE2 + row;
            int dl = __ldg(dstp + e);
            float4 z = *reinterpret_cast<const float4*>(stg + row * FPAD + lane * 4);
            __stcs(reinterpret_cast<float4*>(Zo + (size_t)e * HH + lane * 4), z);
            atomicAdd(reinterpret_cast<float4*>(nZo + (size_t)dl * HH + lane * 4), z);
        }
        __syncthreads();
    }
}

// ---------------- final msg + node aggregation -------------------------------
__global__ void final_msg(
    const float* __restrict__ msg_input,
    const float* __restrict__ Z, const float* __restrict__ nodeZ,
    const int* __restrict__ src, const int* __restrict__ dst,
    float* __restrict__ m)
{
    int idx = blockIdx.x * 256 + threadIdx.x;
    int e = idx >> 5, q = idx & 31;
    float4 v = __ldcs(reinterpret_cast<const float4*>(msg_input) + (size_t)e * 32 + q);
    float4 a = __ldg(reinterpret_cast<const float4*>(nodeZ) + (size_t)__ldg(src + e) * 32 + q);
    float4 b = __ldcs(reinterpret_cast<const float4*>(Z) + (size_t)(e ^ 1) * 32 + q);
    float4 r = make_float4(fmaxf(v.x + a.x - b.x, 0.f),
                           fmaxf(v.y + a.y - b.y, 0.f),
                           fmaxf(v.z + a.z - b.z, 0.f),
                           fmaxf(v.w + a.w - b.w, 0.f));
    atomicAdd(reinterpret_cast<float4*>(m + (size_t)__ldg(dst + e) * HH + q * 4), r);
}

// ---------------- readout via mma.sync bf16-split ----------------------------
__global__ __launch_bounds__(256, 1) void node_out_mma(
    const float* __restrict__ atom_x, const float* __restrict__ m,
    const int* __restrict__ gids, const float* __restrict__ Wo,
    const float* __restrict__ b_o, const float* __restrict__ inv,
    float* __restrict__ out)
{
    extern __shared__ char smc[];
    char* wih = smc;
    char* wil = smc + N_OFF_WHL;
    char* mh  = smc + N_OFF_MH;
    char* ml  = smc + N_OFF_ML;
    float* stg = (float*)(smc + N_OFF_STG);

    int tid = threadIdx.x, lane = tid & 31, wid = tid >> 5;
    int wm = wid >> 2, wn = wid & 3;

    for (int idx = tid; idx < 128 * 44; idx += 256) {
        int n = idx / 44, c4 = (idx % 44) * 4;
        float4 v;
#pragma unroll
        for (int c = 0; c < 4; c++) {
            int p = c4 + c;
            float val = 0.f;
            if (p < KO) {
                int oc = (p < HH) ? (p + AF) : (p - HH);
                val = Wo[(size_t)n * KO + oc];
            }
            (&v.x)[c] = val;
        }
        split_store_s(wih, wil, n, c4, v, SP2);
    }
    __syncthreads();

    int g = lane >> 2, t2 = (lane & 3) * 2;
    int wrow = wid * 8;

    uint32_t mh_b = smem_u32(mh), ml_b = smem_u32(ml);
    uint32_t wih_b = smem_u32(wih), wil_b = smem_u32(wil);
    uint32_t a_off = (uint32_t)(32 * wm + (lane & 15)) * (SP2 * 2)
                   + ((lane >> 4) << 4);
    uint32_t b_off = (uint32_t)(32 * wn + (lane & 7)) * (SP2 * 2)
                   + (((lane >> 3) & 1) << 4);

    const float4* m4 = reinterpret_cast<const float4*>(m);
    const int NTN = NN / 64;

    for (int t = blockIdx.x; t < NTN; t += gridDim.x) {
#pragma unroll
        for (int i = 0; i < 8; i++) {
            int row = wrow + i;
            int v = t * 64 + row;
            float4 mv = __ldcs(m4 + (size_t)v * 32 + lane);
            split_store_s(mh, ml, row, lane * 4, mv, SP2);
            if (lane < 12) {
                int c4 = 128 + lane * 4;
                float4 av;
#pragma unroll
                for (int c = 0; c < 4; c++) {
                    int a = c4 + c - 128;
                    (&av.x)[c] = (a < AF) ? __ldg(atom_x + (size_t)v * AF + a) : 0.f;
                }
                split_store_s(mh, ml, row, c4, av, SP2);
            }
        }
        __syncthreads();

        MMA_CORE(11, SP2, wih_b, wil_b, mh_b, ml_b)
        __syncthreads();

        STAGE_ACC()
        __syncthreads();

        float4 b = *reinterpret_cast<const float4*>(b_o + lane * 4);
#pragma unroll
        for (int i = 0; i < 8; i++) {
            int row = wrow + i;
            int v = t * 64 + row;
            int gg = __ldg(gids + v);
            float iv = __ldg(inv + gg);
            float4 z = *reinterpret_cast<const float4*>(stg + row * FPAD + lane * 4);
            float4 h = make_float4(fmaxf(z.x + b.x, 0.f) * iv,
                                   fmaxf(z.y + b.y, 0.f) * iv,
                                   fmaxf(z.z + b.z, 0.f) * iv,
                                   fmaxf(z.w + b.w, 0.f) * iv);
            atomicAdd(reinterpret_cast<float4*>(out + (size_t)gg * HH + lane * 4), h);
        }
        __syncthreads();
    }
}

// ---------------- launch -----------------------------------------------------
extern "C" void kernel_launch(void* const* d_in, const int* in_sizes, int n_in,
                              void* d_out, int out_size) {
    const float* atom_x = (const float*)d_in[0];
    const float* bond_x = (const float*)d_in[1];
    const int*   src    = (const int*)d_in[2];
    const int*   dst    = (const int*)d_in[3];
    const int*   gids   = (const int*)d_in[4];
    const float* W_i    = (const float*)d_in[5];
    const float* W_h    = (const float*)d_in[6];
    const float* W_o    = (const float*)d_in[7];
    const float* b_o    = (const float*)d_in[8];
    float* out = (float*)d_out;

    void *p_mi, *p_z0, *p_z1, *p_n0, *p_n1, *p_n2, *p_m, *p_inv, *p_cnt;
    cudaGetSymbolAddress(&p_mi, g_msg_input);
    cudaGetSymbolAddress(&p_z0, g_Z0);
    cudaGetSymbolAddress(&p_z1, g_Z1);
    cudaGetSymbolAddress(&p_n0, g_nZ0);
    cudaGetSymbolAddress(&p_n1, g_nZ1);
    cudaGetSymbolAddress(&p_n2, g_nZ2);
    cudaGetSymbolAddress(&p_m,  g_m);
    cudaGetSymbolAddress(&p_inv, g_inv);
    cudaGetSymbolAddress(&p_cnt, g_cnt);
    cudaFuncSetAttribute(fused_step_mma, cudaFuncAttributeMaxDynamicSharedMemorySize, TC_SMEM);
    cudaFuncSetAttribute(mk_step0_mma, cudaFuncAttributeMaxDynamicSharedMemorySize, MS_SMEM);
    cudaFuncSetAttribute(node_out_mma, cudaFuncAttributeMaxDynamicSharedMemorySize, N_SMEM);

    cudaMemsetAsync(p_cnt, 0, NG * sizeof(int));
    cudaMemsetAsync(out, 0, (size_t)out_size * sizeof(float));

    // count per-graph nodes + zero nZ0 (RED target of merged step 0)
    prep_k<<<1184, 256>>>(gids, (int*)p_cnt, (float*)p_n0);
    inv_k<<<(NG + 255) / 256, 256>>>((const int*)p_cnt, (float*)p_inv);

    // merged: build mi + step 0 (Z0 -> Zb[0], RED -> Nb[0], zero Nb[1])
    mk_step0_mma<<<148, 256, MS_SMEM>>>(atom_x, bond_x, src, dst, W_i, W_h,
                                        (float*)p_mi, (float*)p_z0,
                                        (float*)p_n0, (float*)p_n1);

    float* Zb[2] = {(float*)p_z0, (float*)p_z1};
    float* Nb[3] = {(float*)p_n0, (float*)p_n1, (float*)p_n2};
    for (int t = 1; t < DEPTH - 1; t++) {
        // step t: reads Nb[(t+2)%3], REDs Nb[t%3] (zeroed by step t-1),
        // zeroes Nb[(t+1)%3] (g_m at the last step)
        float* zbuf = (t == DEPTH - 2) ? (float*)p_m : Nb[(t + 1) % 3];
        int rev = (t & 1) ? 0 : 1;
        fused_step_mma<<<GRID_TC, 256, TC_SMEM>>>(
            (const float*)p_mi, Zb[(t + 1) & 1], Nb[(t + 2) % 3],
            Zb[t & 1], Nb[t % 3], zbuf, NN * 32, W_h, src, dst, rev);
    }
    // after t=4: Z = Zb[0], nodeZ = Nb[1], g_m zeroed

    final_msg<<<(NE * 32) / 256, 256>>>((const float*)p_mi, Zb[0], Nb[1],
                                        src, dst, (float*)p_m);

    node_out_mma<<<148, 256, N_SMEM>>>(atom_x, (const float*)p_m, gids,
                                       W_o, b_o, (const float*)p_inv, out);
}

// round 17
// speedup vs baseline: 1.0850x; 1.0850x over previous
#include <cuda_runtime.h>
#include <cuda_bf16.h>
#include <cstdint>

// Problem constants (fixed by setup_inputs)
#define NN 200000      // nodes
#define NE 800000      // edges
#define HH 128         // hidden
#define NG 8000        // graphs
#define AF 39          // atom feature dim
#define BF 11          // bond feature dim
#define KI 50          // AF+BF
#define KO 167         // AF+HH
#define DEPTH 6
#define TE2 64         // edges per tensor tile
#define NTT (NE / TE2) // 12500
#define GRID_TC 296

#define SPAD 136       // bf16 tile row stride (elements); 272B rows
#define FPAD 132       // f32 staging row stride (elements)

// smem byte offsets: [W_hi 34816][W_lo 34816][msg_hi 17408][msg_lo 17408]
// f32 staging (33792 B) overlays the msg hi+lo region (34816 B).
#define OFF_WHL 34816
#define OFF_MH  69632
#define OFF_ML  87040
#define OFF_STG 69632
#define TC_SMEM 104448

// node_out MMA tile geometry: K padded 167 -> 176, stride 184 elems (368 B)
#define SP2 184
#define N_OFF_WHL 47104
#define N_OFF_MH  94208
#define N_OFF_ML  117760
#define N_OFF_STG 94208
#define N_SMEM    141312

// ---------------- scratch (device globals; no allocations allowed) ----------
__device__ float g_msg_input[(size_t)NE * HH];
__device__ float g_Z0[(size_t)NE * HH];
__device__ float g_Z1[(size_t)NE * HH];
__device__ float g_nZ0[(size_t)NN * HH];
__device__ float g_nZ1[(size_t)NN * HH];
__device__ float g_nZ2[(size_t)NN * HH];
__device__ float g_m[(size_t)NN * HH];
__device__ float g_inv[NG];
__device__ int   g_cnt[NG];

// ---------------- mma.sync / ldmatrix helpers (arch-agnostic PTX) ------------
__device__ __forceinline__ uint32_t smem_u32(const void* p) {
    uint32_t a;
    asm("{ .reg .u64 t; cvta.to.shared.u64 t, %1; cvt.u32.u64 %0, t; }"
        : "=r"(a) : "l"(p));
    return a;
}
#define LDSM_X4(r0, r1, r2, r3, addr) \
    asm volatile("ldmatrix.sync.aligned.m8n8.x4.shared.b16 {%0,%1,%2,%3}, [%4];" \
        : "=r"(r0), "=r"(r1), "=r"(r2), "=r"(r3) : "r"(addr))
#define LDSM_X2(r0, r1, addr) \
    asm volatile("ldmatrix.sync.aligned.m8n8.x2.shared.b16 {%0,%1}, [%2];" \
        : "=r"(r0), "=r"(r1) : "r"(addr))

__device__ __forceinline__ void mma_bf16(float* d, const uint32_t* a,
                                         const uint32_t* b) {
    asm volatile(
        "mma.sync.aligned.m16n8k16.row.col.f32.bf16.bf16.f32 "
        "{%0,%1,%2,%3}, {%4,%5,%6,%7}, {%8,%9}, {%0,%1,%2,%3};"
        : "+f"(d[0]), "+f"(d[1]), "+f"(d[2]), "+f"(d[3])
        : "r"(a[0]), "r"(a[1]), "r"(a[2]), "r"(a[3]), "r"(b[0]), "r"(b[1]));
}

__device__ __forceinline__ unsigned bfpair(float lo, float hi) {
    unsigned r;
    asm("cvt.rn.bf16x2.f32 %0, %1, %2;" : "=r"(r) : "f"(hi), "f"(lo));
    return r;
}
__device__ __forceinline__ unsigned long long pku(unsigned a, unsigned b) {
    unsigned long long r;
    asm("mov.b64 %0, {%1, %2};" : "=l"(r) : "r"(a), "r"(b));
    return r;
}
// split float4 into hi/lo bf16 quads, store row-major stride SPAD at (row, col4)
__device__ __forceinline__ void split_store(char* mh, char* ml, int row, int col4,
                                            float4 v) {
    __nv_bfloat16 b0 = __float2bfloat16_rn(v.x), b1 = __float2bfloat16_rn(v.y);
    __nv_bfloat16 b2 = __float2bfloat16_rn(v.z), b3 = __float2bfloat16_rn(v.w);
    unsigned hp01 = (unsigned)__bfloat16_as_ushort(b0)
                  | ((unsigned)__bfloat16_as_ushort(b1) << 16);
    unsigned hp23 = (unsigned)__bfloat16_as_ushort(b2)
                  | ((unsigned)__bfloat16_as_ushort(b3) << 16);
    float l0 = v.x - __bfloat162float(b0), l1 = v.y - __bfloat162float(b1);
    float l2 = v.z - __bfloat162float(b2), l3 = v.w - __bfloat162float(b3);
    uint32_t off = (uint32_t)row * (SPAD * 2) + (uint32_t)col4 * 2;
    *(unsigned long long*)(mh + off) = pku(hp01, hp23);
    *(unsigned long long*)(ml + off) = pku(bfpair(l0, l1), bfpair(l2, l3));
}
// same but parameterized stride (elements)
__device__ __forceinline__ void split_store_s(char* mh, char* ml, int row, int col4,
                                              float4 v, int spad) {
    __nv_bfloat16 b0 = __float2bfloat16_rn(v.x), b1 = __float2bfloat16_rn(v.y);
    __nv_bfloat16 b2 = __float2bfloat16_rn(v.z), b3 = __float2bfloat16_rn(v.w);
    unsigned hp01 = (unsigned)__bfloat16_as_ushort(b0)
                  | ((unsigned)__bfloat16_as_ushort(b1) << 16);
    unsigned hp23 = (unsigned)__bfloat16_as_ushort(b2)
                  | ((unsigned)__bfloat16_as_ushort(b3) << 16);
    float l0 = v.x - __bfloat162float(b0), l1 = v.y - __bfloat162float(b1);
    float l2 = v.z - __bfloat162float(b2), l3 = v.w - __bfloat162float(b3);
    uint32_t off = (uint32_t)row * (spad * 2) + (uint32_t)col4 * 2;
    *(unsigned long long*)(mh + off) = pku(hp01, hp23);
    *(unsigned long long*)(ml + off) = pku(bfpair(l0, l1), bfpair(l2, l3));
}

// ---------------- small kernels ---------------------------------------------
__global__ void count_k(const int* __restrict__ gid, int* __restrict__ cnt) {
    int v = blockIdx.x * 256 + threadIdx.x;
    if (v < NN) atomicAdd(&cnt[gid[v]], 1);
}
__global__ void inv_k(const int* __restrict__ cnt, float* __restrict__ inv) {
    int g = blockIdx.x * 256 + threadIdx.x;
    if (g < NG) inv[g] = 1.0f / fmaxf((float)cnt[g], 1.0f);
}

// ============ shared MMA core: 64 rows x 128 cols, 2Mx4N warp split =========
#define MMA_CORE(NKK, spadv, whib, whilb, mhb, mlb)                            \
    float acc[2][4][4];                                                        \
    _Pragma("unroll")                                                          \
    for (int rt = 0; rt < 2; rt++)                                             \
        _Pragma("unroll")                                                      \
        for (int jj = 0; jj < 4; jj++) {                                       \
            acc[rt][jj][0] = 0.f; acc[rt][jj][1] = 0.f;                        \
            acc[rt][jj][2] = 0.f; acc[rt][jj][3] = 0.f;                        \
        }                                                                      \
    _Pragma("unroll 1")                                                        \
    for (int kk = 0; kk < NKK; kk++) {                                         \
        uint32_t koff = (uint32_t)kk * 32;                                     \
        uint32_t bh[4][2], bl[4][2];                                           \
        _Pragma("unroll")                                                      \
        for (int jj = 0; jj < 4; jj++) {                                       \
            uint32_t boff = b_off + (uint32_t)(8 * jj) * (spadv * 2) + koff;   \
            LDSM_X2(bh[jj][0], bh[jj][1], whib + boff);                        \
            LDSM_X2(bl[jj][0], bl[jj][1], whilb + boff);                       \
        }                                                                      \
        _Pragma("unroll")                                                      \
        for (int rt = 0; rt < 2; rt++) {                                       \
            uint32_t aaddr = a_off + (uint32_t)(16 * rt) * (spadv * 2) + koff; \
            uint32_t ah[4], al[4];                                             \
            LDSM_X4(ah[0], ah[1], ah[2], ah[3], mhb + aaddr);                  \
            LDSM_X4(al[0], al[1], al[2], al[3], mlb + aaddr);                  \
            _Pragma("unroll")                                                  \
            for (int jj = 0; jj < 4; jj++) {                                   \
                mma_bf16(acc[rt][jj], ah, bh[jj]);                             \
                mma_bf16(acc[rt][jj], ah, bl[jj]);                             \
                mma_bf16(acc[rt][jj], al, bh[jj]);                             \
            }                                                                  \
        }                                                                      \
    }

#define STAGE_ACC()                                                            \
    _Pragma("unroll")                                                          \
    for (int rt = 0; rt < 2; rt++)                                             \
        _Pragma("unroll")                                                      \
        for (int jj = 0; jj < 4; jj++) {                                       \
            int col = 32 * wn + 8 * jj + t2;                                   \
            int r0 = 32 * wm + 16 * rt + g;                                    \
            *reinterpret_cast<float2*>(stg + r0 * FPAD + col)                  \
                = make_float2(acc[rt][jj][0], acc[rt][jj][1]);                 \
            *reinterpret_cast<float2*>(stg + (r0 + 8) * FPAD + col)           \
                = make_float2(acc[rt][jj][2], acc[rt][jj][3]);                 \
        }

// ---------------- msg_input via mma.sync bf16-split --------------------------
__global__ __launch_bounds__(256, 2) void mk_msg_input_mma(
    const float* __restrict__ atom_x, const float* __restrict__ bond_x,
    const int* __restrict__ srcp, const float* __restrict__ Wi,
    float* __restrict__ mi, float* __restrict__ nZzero)
{
    extern __shared__ char smc[];
    char* wih = smc;
    char* wil = smc + OFF_WHL;
    char* mh  = smc + OFF_MH;
    char* ml  = smc + OFF_ML;
    float* stg = (float*)(smc + OFF_STG);

    int tid = threadIdx.x, lane = tid & 31, wid = tid >> 5;
    int wm = wid >> 2, wn = wid & 3;

    {
        float4* zz = reinterpret_cast<float4*>(nZzero);
        float4 z4 = make_float4(0.f, 0.f, 0.f, 0.f);
        for (int i = blockIdx.x * 256 + tid; i < NN * 32; i += gridDim.x * 256)
            __stcs(zz + i, z4);
    }

    // Wi (fp32 [128][50]) -> bf16 hi/lo tiles, rows n, cols k padded to 64
    for (int idx = tid; idx < 128 * 16; idx += 256) {
        int n = idx >> 4, c4 = (idx & 15) * 4;
        float4 v;
        v.x = (c4 + 0 < KI) ? Wi[(size_t)n * KI + c4 + 0] : 0.f;
        v.y = (c4 + 1 < KI) ? Wi[(size_t)n * KI + c4 + 1] : 0.f;
        v.z = (c4 + 2 < KI) ? Wi[(size_t)n * KI + c4 + 2] : 0.f;
        v.w = (c4 + 3 < KI) ? Wi[(size_t)n * KI + c4 + 3] : 0.f;
        split_store(wih, wil, n, c4, v);
    }
    __syncthreads();

    int g = lane >> 2, t2 = (lane & 3) * 2;
    int wrow = wid * 8;

    uint32_t mh_b = smem_u32(mh), ml_b = smem_u32(ml);
    uint32_t wih_b = smem_u32(wih), wil_b = smem_u32(wil);
    uint32_t a_off = (uint32_t)(32 * wm + (lane & 15)) * (SPAD * 2)
                   + ((lane >> 4) << 4);
    uint32_t b_off = (uint32_t)(32 * wn + (lane & 7)) * (SPAD * 2)
                   + (((lane >> 3) & 1) << 4);

    for (int t = blockIdx.x; t < NTT; t += gridDim.x) {
#pragma unroll
        for (int i = 0; i < 4; i++) {
            int row = wrow + i * 2 + (lane >> 4);
            int e = t * TE2 + row;
            int s = __ldg(srcp + e);
            int c0 = (lane & 15) * 4;
            float4 v;
#pragma unroll
            for (int c = 0; c < 4; c++) {
                int cc = c0 + c;
                float val = 0.f;
                if (cc < AF)      val = __ldg(atom_x + (size_t)s * AF + cc);
                else if (cc < KI) val = __ldg(bond_x + (size_t)e * BF + (cc - AF));
                (&v.x)[c] = val;
            }
            split_store(mh, ml, row, c0, v);
        }
        __syncthreads();

        MMA_CORE(4, SPAD, wih_b, wil_b, mh_b, ml_b)
        __syncthreads();

        STAGE_ACC()
        __syncthreads();

#pragma unroll
        for (int i = 0; i < 8; i++) {
            int row = wrow + i;
            int e = t * TE2 + row;
            float4 z = *reinterpret_cast<const float4*>(stg + row * FPAD + lane * 4);
            __stcs(reinterpret_cast<float4*>(mi + (size_t)e * HH + lane * 4), z);
        }
        __syncthreads();
    }
}

// ---------------- fused BP step via mma.sync bf16-split ----------------------
// Combine loads are issued in 4-row batches (12 independent float4 LDGs in
// flight per warp) to hide gather latency; everything else is R14 structure.
__global__ __launch_bounds__(256, 2) void fused_step_mma(
    const float* __restrict__ mi, const float* __restrict__ Zp,
    const float* __restrict__ nZp, float* __restrict__ Zo,
    float* __restrict__ nZo, float* __restrict__ nZzero, int zero_n,
    const float* __restrict__ Wh,
    const int* __restrict__ srcp, const int* __restrict__ dstp,
    int first, int rev)
{
    extern __shared__ char smc[];
    char* whh = smc;
    char* whl = smc + OFF_WHL;
    char* mh  = smc + OFF_MH;
    char* ml  = smc + OFF_ML;
    float* stg = (float*)(smc + OFF_STG);

    int tid = threadIdx.x, lane = tid & 31, wid = tid >> 5;
    int wm = wid >> 2, wn = wid & 3;

    {
        float4* zz = reinterpret_cast<float4*>(nZzero);
        float4 z4 = make_float4(0.f, 0.f, 0.f, 0.f);
        for (int i = blockIdx.x * 256 + tid; i < zero_n; i += gridDim.x * 256)
            __stcs(zz + i, z4);
    }

    for (int n0 = wid * 16; n0 < wid * 16 + 16; n0++) {
        float4 w = *reinterpret_cast<const float4*>(Wh + (size_t)n0 * HH + lane * 4);
        split_store(whh, whl, n0, lane * 4, w);
    }
    __syncthreads();

    const float4* mi4 = reinterpret_cast<const float4*>(mi);
    const float4* nz4 = reinterpret_cast<const float4*>(nZp);
    const float4* zp4 = reinterpret_cast<const float4*>(Zp);

    int g = lane >> 2, t2 = (lane & 3) * 2;
    int wrow = wid * 8;

    uint32_t mh_b = smem_u32(mh), ml_b = smem_u32(ml);
    uint32_t whh_b = smem_u32(whh), whl_b = smem_u32(whl);
    uint32_t a_off = (uint32_t)(32 * wm + (lane & 15)) * (SPAD * 2)
                   + ((lane >> 4) << 4);
    uint32_t b_off = (uint32_t)(32 * wn + (lane & 7)) * (SPAD * 2)
                   + (((lane >> 3) & 1) << 4);

    for (int it = blockIdx.x; it < NTT; it += gridDim.x) {
        int t = rev ? (NTT - 1 - it) : it;

        // ---- combine: 2 batches of 4 rows, loads issued up-front ----
#pragma unroll
        for (int h = 0; h < 2; h++) {
            float4 v[4], a[4], b[4];
#pragma unroll
            for (int i = 0; i < 4; i++) {
                int e = t * TE2 + wrow + h * 4 + i;
                v[i] = __ldcs(mi4 + (size_t)e * 32 + lane);
                if (!first) {
                    int s = __ldg(srcp + e);
                    a[i] = __ldg(nz4 + (size_t)s * 32 + lane);
                    b[i] = __ldcs(zp4 + (size_t)(e ^ 1) * 32 + lane);
                }
            }
#pragma unroll
            for (int i = 0; i < 4; i++) {
                float4 w = v[i];
                if (!first) {
                    w.x += a[i].x - b[i].x; w.y += a[i].y - b[i].y;
                    w.z += a[i].z - b[i].z; w.w += a[i].w - b[i].w;
                }
                w.x = fmaxf(w.x, 0.f); w.y = fmaxf(w.y, 0.f);
                w.z = fmaxf(w.z, 0.f); w.w = fmaxf(w.w, 0.f);
                split_store(mh, ml, wrow + h * 4 + i, lane * 4, w);
            }
        }
        __syncthreads();

        MMA_CORE(8, SPAD, whh_b, whl_b, mh_b, ml_b)
        __syncthreads();

        STAGE_ACC()
        __syncthreads();

#pragma unroll
        for (int i = 0; i < 8; i++) {
            int row = wrow + i;
            int e = t * TE2 + row;
            int dl = __ldg(dstp + e);
            float4 z = *reinterpret_cast<const float4*>(stg + row * FPAD + lane * 4);
            __stcs(reinterpret_cast<float4*>(Zo + (size_t)e * HH + lane * 4), z);
            atomicAdd(reinterpret_cast<float4*>(nZo + (size_t)dl * HH + lane * 4), z);
        }
        __syncthreads();
    }
}

// ---------------- final msg + node aggregation -------------------------------
__global__ void final_msg(
    const float* __restrict__ msg_input,
    const float* __restrict__ Z, const float* __restrict__ nodeZ,
    const int* __restrict__ src, const int* __restrict__ dst,
    float* __restrict__ m)
{
    int idx = blockIdx.x * 256 + threadIdx.x;
    int e = idx >> 5, q = idx & 31;
    float4 v = __ldcs(reinterpret_cast<const float4*>(msg_input) + (size_t)e * 32 + q);
    float4 a = __ldg(reinterpret_cast<const float4*>(nodeZ) + (size_t)__ldg(src + e) * 32 + q);
    float4 b = __ldcs(reinterpret_cast<const float4*>(Z) + (size_t)(e ^ 1) * 32 + q);
    float4 r = make_float4(fmaxf(v.x + a.x - b.x, 0.f),
                           fmaxf(v.y + a.y - b.y, 0.f),
                           fmaxf(v.z + a.z - b.z, 0.f),
                           fmaxf(v.w + a.w - b.w, 0.f));
    atomicAdd(reinterpret_cast<float4*>(m + (size_t)__ldg(dst + e) * HH + q * 4), r);
}

// ---------------- readout via mma.sync bf16-split ----------------------------
__global__ __launch_bounds__(256, 1) void node_out_mma(
    const float* __restrict__ atom_x, const float* __restrict__ m,
    const int* __restrict__ gids, const float* __restrict__ Wo,
    const float* __restrict__ b_o, const float* __restrict__ inv,
    float* __restrict__ out)
{
    extern __shared__ char smc[];
    char* wih = smc;
    char* wil = smc + N_OFF_WHL;
    char* mh  = smc + N_OFF_MH;
    char* ml  = smc + N_OFF_ML;
    float* stg = (float*)(smc + N_OFF_STG);

    int tid = threadIdx.x, lane = tid & 31, wid = tid >> 5;
    int wm = wid >> 2, wn = wid & 3;

    for (int idx = tid; idx < 128 * 44; idx += 256) {
        int n = idx / 44, c4 = (idx % 44) * 4;
        float4 v;
#pragma unroll
        for (int c = 0; c < 4; c++) {
            int p = c4 + c;
            float val = 0.f;
            if (p < KO) {
                int oc = (p < HH) ? (p + AF) : (p - HH);
                val = Wo[(size_t)n * KO + oc];
            }
            (&v.x)[c] = val;
        }
        split_store_s(wih, wil, n, c4, v, SP2);
    }
    __syncthreads();

    int g = lane >> 2, t2 = (lane & 3) * 2;
    int wrow = wid * 8;

    uint32_t mh_b = smem_u32(mh), ml_b = smem_u32(ml);
    uint32_t wih_b = smem_u32(wih), wil_b = smem_u32(wil);
    uint32_t a_off = (uint32_t)(32 * wm + (lane & 15)) * (SP2 * 2)
                   + ((lane >> 4) << 4);
    uint32_t b_off = (uint32_t)(32 * wn + (lane & 7)) * (SP2 * 2)
                   + (((lane >> 3) & 1) << 4);

    const float4* m4 = reinterpret_cast<const float4*>(m);
    const int NTN = NN / 64;

    for (int t = blockIdx.x; t < NTN; t += gridDim.x) {
#pragma unroll
        for (int i = 0; i < 8; i++) {
            int row = wrow + i;
            int v = t * 64 + row;
            float4 mv = __ldcs(m4 + (size_t)v * 32 + lane);
            split_store_s(mh, ml, row, lane * 4, mv, SP2);
            if (lane < 12) {
                int c4 = 128 + lane * 4;
                float4 av;
#pragma unroll
                for (int c = 0; c < 4; c++) {
                    int a = c4 + c - 128;
                    (&av.x)[c] = (a < AF) ? __ldg(atom_x + (size_t)v * AF + a) : 0.f;
                }
                split_store_s(mh, ml, row, c4, av, SP2);
            }
        }
        __syncthreads();

        MMA_CORE(11, SP2, wih_b, wil_b, mh_b, ml_b)
        __syncthreads();

        STAGE_ACC()
        __syncthreads();

        float4 b = *reinterpret_cast<const float4*>(b_o + lane * 4);
#pragma unroll
        for (int i = 0; i < 8; i++) {
            int row = wrow + i;
            int v = t * 64 + row;
            int gg = __ldg(gids + v);
            float iv = __ldg(inv + gg);
            float4 z = *reinterpret_cast<const float4*>(stg + row * FPAD + lane * 4);
            float4 h = make_float4(fmaxf(z.x + b.x, 0.f) * iv,
                                   fmaxf(z.y + b.y, 0.f) * iv,
                                   fmaxf(z.z + b.z, 0.f) * iv,
                                   fmaxf(z.w + b.w, 0.f) * iv);
            atomicAdd(reinterpret_cast<float4*>(out + (size_t)gg * HH + lane * 4), h);
        }
        __syncthreads();
    }
}

// ---------------- launch -----------------------------------------------------
extern "C" void kernel_launch(void* const* d_in, const int* in_sizes, int n_in,
                              void* d_out, int out_size) {
    const float* atom_x = (const float*)d_in[0];
    const float* bond_x = (const float*)d_in[1];
    const int*   src    = (const int*)d_in[2];
    const int*   dst    = (const int*)d_in[3];
    const int*   gids   = (const int*)d_in[4];
    const float* W_i    = (const float*)d_in[5];
    const float* W_h    = (const float*)d_in[6];
    const float* W_o    = (const float*)d_in[7];
    const float* b_o    = (const float*)d_in[8];
    float* out = (float*)d_out;

    void *p_mi, *p_z0, *p_z1, *p_n0, *p_n1, *p_n2, *p_m, *p_inv, *p_cnt;
    cudaGetSymbolAddress(&p_mi, g_msg_input);
    cudaGetSymbolAddress(&p_z0, g_Z0);
    cudaGetSymbolAddress(&p_z1, g_Z1);
    cudaGetSymbolAddress(&p_n0, g_nZ0);
    cudaGetSymbolAddress(&p_n1, g_nZ1);
    cudaGetSymbolAddress(&p_n2, g_nZ2);
    cudaGetSymbolAddress(&p_m,  g_m);
    cudaGetSymbolAddress(&p_inv, g_inv);
    cudaGetSymbolAddress(&p_cnt, g_cnt);
    cudaFuncSetAttribute(fused_step_mma, cudaFuncAttributeMaxDynamicSharedMemorySize, TC_SMEM);
    cudaFuncSetAttribute(mk_msg_input_mma, cudaFuncAttributeMaxDynamicSharedMemorySize, TC_SMEM);
    cudaFuncSetAttribute(node_out_mma, cudaFuncAttributeMaxDynamicSharedMemorySize, N_SMEM);

    cudaMemsetAsync(p_cnt, 0, NG * sizeof(int));
    cudaMemsetAsync(out, 0, (size_t)out_size * sizeof(float));

    count_k<<<(NN + 255) / 256, 256>>>(gids, (int*)p_cnt);
    inv_k<<<(NG + 255) / 256, 256>>>((const int*)p_cnt, (float*)p_inv);

    mk_msg_input_mma<<<GRID_TC, 256, TC_SMEM>>>(atom_x, bond_x, src, W_i,
                                                (float*)p_mi, (float*)p_n0);

    float* Zb[2] = {(float*)p_z0, (float*)p_z1};
    float* Nb[3] = {(float*)p_n0, (float*)p_n1, (float*)p_n2};
    for (int t = 0; t < DEPTH - 1; t++) {
        float* zbuf = (t == DEPTH - 2) ? (float*)p_m : Nb[(t + 1) % 3];
        int rev = (t & 1) ? 0 : 1;
        fused_step_mma<<<GRID_TC, 256, TC_SMEM>>>(
            (const float*)p_mi, Zb[(t + 1) & 1], Nb[(t + 2) % 3],
            Zb[t & 1], Nb[t % 3], zbuf, NN * 32, W_h, src, dst, t == 0, rev);
    }
    // after t=4: Z = Zb[0], nodeZ = Nb[1], g_m zeroed

    final_msg<<<(NE * 32) / 256, 256>>>((const float*)p_mi, Zb[0], Nb[1],
                                        src, dst, (float*)p_m);

    node_out_mma<<<148, 256, N_SMEM>>>(atom_x, (const float*)p_m, gids,
                                       W_o, b_o, (const float*)p_inv, out);
}